// round 16
// baseline (speedup 1.0000x reference)
#include <cuda_runtime.h>
#include <cuda_fp16.h>
#include <math.h>

#define BB 4
#define SS 2048
#define DD 1024
#define HH 16
#define DP 64
#define MM (BB*SS)

static const long long OUT_ELEMS  = (long long)BB*SS*DD;
static const long long ATTN_ELEMS = (long long)BB*HH*(long long)SS*SS;

// Scratch (__device__ globals per allocation rules)
__device__ __half g_Qh16[BB*HH*SS*DP];   // head-split Q, fp16
__device__ __half g_Kh16[BB*HH*SS*DP];   // head-split K, fp16
__device__ float  g_Vh[BB*HH*SS*DP];     // head-split V, fp32
__device__ float  g_ctx[BB*SS*DD];
__device__ float  g_attn[BB*HH*(long long)SS*SS];

// ---------------------------------------------------------------------------
__device__ __forceinline__ unsigned f2tf(float x) {
    unsigned r;
    asm("cvt.rna.tf32.f32 %0, %1;" : "=r"(r) : "f"(x));
    return r;
}
__device__ __forceinline__ unsigned raw2tf(unsigned x) {
    return f2tf(__uint_as_float(x));
}

__device__ __forceinline__ void mma_tf32(float c[4], const unsigned a[4], const unsigned b[2]) {
    asm volatile(
        "mma.sync.aligned.m16n8k8.row.col.f32.tf32.tf32.f32 "
        "{%0,%1,%2,%3}, {%4,%5,%6,%7}, {%8,%9}, {%0,%1,%2,%3};"
        : "+f"(c[0]), "+f"(c[1]), "+f"(c[2]), "+f"(c[3])
        : "r"(a[0]), "r"(a[1]), "r"(a[2]), "r"(a[3]), "r"(b[0]), "r"(b[1]));
}

__device__ __forceinline__ void mma_f16(float c[4], const unsigned a[4], const unsigned b[2]) {
    asm volatile(
        "mma.sync.aligned.m16n8k16.row.col.f32.f16.f16.f32 "
        "{%0,%1,%2,%3}, {%4,%5,%6,%7}, {%8,%9}, {%0,%1,%2,%3};"
        : "+f"(c[0]), "+f"(c[1]), "+f"(c[2]), "+f"(c[3])
        : "r"(a[0]), "r"(a[1]), "r"(a[2]), "r"(a[3]), "r"(b[0]), "r"(b[1]));
}

__device__ __forceinline__ void ldsm_x4(unsigned r[4], const void* p) {
    unsigned addr = (unsigned)__cvta_generic_to_shared(p);
    asm volatile("ldmatrix.sync.aligned.m8n8.x4.shared.b16 {%0,%1,%2,%3}, [%4];"
                 : "=r"(r[0]), "=r"(r[1]), "=r"(r[2]), "=r"(r[3]) : "r"(addr));
}

__device__ __forceinline__ void cp_async16(void* smem, const void* gmem) {
    unsigned s = (unsigned)__cvta_generic_to_shared(smem);
    asm volatile("cp.async.ca.shared.global [%0], [%1], 16;" :: "r"(s), "l"(gmem));
}
__device__ __forceinline__ void cp_commit() {
    asm volatile("cp.async.commit_group;");
}
template<int N>
__device__ __forceinline__ void cp_wait() {
    asm volatile("cp.async.wait_group %0;" :: "n"(N));
}

// ---------------------------------------------------------------------------
// Pipelined TF32 tensor-core GEMM (R10-proven):  C = alpha * A @ op(B) + bias
//  SPLIT: 0 = plain; 1 = head-split fp32 [b,h,s,d]; 2 = merged ctx;
//         4 = head-split fp16 store (C reinterpreted as __half*).
// ---------------------------------------------------------------------------
template<int BM, int BN, int BK, int WM, int WN, bool BT, int SPLIT, int THREADS>
__global__ __launch_bounds__(THREADS)
void mma_gemm_kernel(const float* __restrict__ A,
                     const float* __restrict__ Bm,
                     const float* __restrict__ bias,
                     float* __restrict__ C,
                     int M, int N, int K,
                     long long sA, long long sB, long long sC,
                     float alpha)
{
    constexpr int AP  = BK + 4;
    constexpr int BP  = BN + 4;
    constexpr int BP2 = BK + 4;
    constexpr int ASZ = BM * AP;
    constexpr int BSZ = BT ? (BN * BP2) : (BK * BP);
    __shared__ __align__(16) unsigned As[2 * ASZ];
    __shared__ __align__(16) unsigned Bs[2 * BSZ];

    const int tid  = threadIdx.x;
    const int lane = tid & 31;
    const int warp = tid >> 5;
    constexpr int WN_CNT = BN / WN;
    const int wm = warp / WN_CNT;
    const int wn = warp % WN_CNT;
    const int row0 = blockIdx.y * BM;
    const int col0 = blockIdx.x * BN;
    const int z    = blockIdx.z;

    A  += (long long)z * sA;
    Bm += (long long)z * sB;

    constexpr int MT = WM / 16;
    constexpr int NT = WN / 8;
    float cfr[MT][NT][4];
#pragma unroll
    for (int mt = 0; mt < MT; mt++)
#pragma unroll
        for (int nt = 0; nt < NT; nt++)
#pragma unroll
            for (int i = 0; i < 4; i++) cfr[mt][nt][i] = 0.0f;

    const int grp  = lane >> 3, rrw = lane & 7;
    const int a_ro = (grp & 1) * 8 + rrw;
    const int a_ko = (grp >> 1) * 4;
    const int b_no = (grp >> 1) * 8 + rrw;
    const int b_ko = (grp & 1) * 4;

    auto load_tiles = [&](int buf, int k0) {
        unsigned* Ad = As + buf * ASZ;
        unsigned* Bd = Bs + buf * BSZ;
#pragma unroll
        for (int i = 0; i < (BM * (BK / 4)) / THREADS; i++) {
            int idx = tid + i * THREADS;
            int r   = idx / (BK / 4);
            int kq  = (idx % (BK / 4)) * 4;
            cp_async16(&Ad[r * AP + kq], A + (long long)(row0 + r) * K + k0 + kq);
        }
        if (BT) {
#pragma unroll
            for (int i = 0; i < (BN * (BK / 4)) / THREADS; i++) {
                int idx = tid + i * THREADS;
                int n   = idx / (BK / 4);
                int kq  = (idx % (BK / 4)) * 4;
                cp_async16(&Bd[n * BP2 + kq], Bm + (long long)(col0 + n) * K + k0 + kq);
            }
        } else {
#pragma unroll
            for (int i = 0; i < (BK * (BN / 4)) / THREADS; i++) {
                int idx = tid + i * THREADS;
                int kk  = idx / (BN / 4);
                int nq  = (idx % (BN / 4)) * 4;
                cp_async16(&Bd[kk * BP + nq], Bm + (long long)(k0 + kk) * N + col0 + nq);
            }
        }
        cp_commit();
    };

    const int NK = K / BK;
    load_tiles(0, 0);

    for (int it = 0; it < NK; it++) {
        if (it + 1 < NK) {
            load_tiles((it + 1) & 1, (it + 1) * BK);
            cp_wait<1>();
        } else {
            cp_wait<0>();
        }
        __syncthreads();

        const unsigned* Ab = As + (it & 1) * ASZ;
        const unsigned* Bb = Bs + (it & 1) * BSZ;
#pragma unroll
        for (int ks = 0; ks < BK / 8; ks++) {
            unsigned af[MT][4];
            unsigned bf[NT][2];
#pragma unroll
            for (int mt = 0; mt < MT; mt++) {
                ldsm_x4(af[mt], &Ab[(wm * WM + mt * 16 + a_ro) * AP + ks * 8 + a_ko]);
#pragma unroll
                for (int j = 0; j < 4; j++) af[mt][j] = raw2tf(af[mt][j]);
            }
            if (BT) {
#pragma unroll
                for (int np = 0; np < NT / 2; np++) {
                    unsigned qv[4];
                    ldsm_x4(qv, &Bb[(wn * WN + np * 16 + b_no) * BP2 + ks * 8 + b_ko]);
                    bf[np * 2 + 0][0] = raw2tf(qv[0]); bf[np * 2 + 0][1] = raw2tf(qv[1]);
                    bf[np * 2 + 1][0] = raw2tf(qv[2]); bf[np * 2 + 1][1] = raw2tf(qv[3]);
                }
            } else {
                const int kb = ks * 8 + (lane & 3);
#pragma unroll
                for (int nt = 0; nt < NT; nt++) {
                    int cc = wn * WN + nt * 8 + (lane >> 2);
                    bf[nt][0] = raw2tf(Bb[kb * BP + cc]);
                    bf[nt][1] = raw2tf(Bb[(kb + 4) * BP + cc]);
                }
            }
#pragma unroll
            for (int mt = 0; mt < MT; mt++)
#pragma unroll
                for (int nt = 0; nt < NT; nt++)
                    mma_tf32(cfr[mt][nt], af[mt], bf[nt]);
        }
        __syncthreads();
    }

    // ---- epilogue
#pragma unroll
    for (int mt = 0; mt < MT; mt++) {
#pragma unroll
        for (int nt = 0; nt < NT; nt++) {
#pragma unroll
            for (int i = 0; i < 4; i++) {
                int r = row0 + wm * WM + mt * 16 + (lane >> 2) + ((i >= 2) ? 8 : 0);
                int c = col0 + wn * WN + nt * 8 + (lane & 3) * 2 + (i & 1);
                float v = cfr[mt][nt][i] * alpha + (bias ? bias[c] : 0.0f);
                if (SPLIT == 0) {
                    C[(long long)z * sC + (long long)r * N + c] = v;
                } else if (SPLIT == 1) {
                    int b = r / SS, s = r % SS;
                    int h = c / DP, d = c % DP;
                    C[(((long long)b * HH + h) * SS + s) * DP + d] = v;
                } else if (SPLIT == 2) {
                    int b = z / HH, h = z % HH;
                    C[((long long)b * SS + r) * DD + h * DP + c] = v;
                } else { // SPLIT == 4 : head-split fp16
                    int b = r / SS, s = r % SS;
                    int h = c / DP, d = c % DP;
                    ((__half*)C)[(((long long)b * HH + h) * SS + s) * DP + d] =
                        __float2half_rn(v);
                }
            }
        }
    }
}

// ---------------------------------------------------------------------------
// QK^T in fp16: logits = 0.125 * Q @ K^T per (b,h).
// One smem stage covers the whole K-depth (64).  m16n8k16.
// Grid (16 k-tiles, 16 q-tiles, 64 bh), 256 thr, warps 2x4 (WM=64, WN=32).
// ---------------------------------------------------------------------------
__global__ __launch_bounds__(256)
void qk16_kernel(const __half* __restrict__ Qg,
                 const __half* __restrict__ Kg,
                 float* __restrict__ attn)
{
    constexpr int STR = 72;   // halves per row: 144 B = 9 x 16B units (odd -> conflict-free)
    __shared__ __align__(16) unsigned short Qs[128 * STR];
    __shared__ __align__(16) unsigned short Ks[128 * STR];

    const int tid  = threadIdx.x;
    const int lane = tid & 31;
    const int warp = tid >> 5;
    const int wm = warp >> 2;   // 0..1
    const int wn = warp & 3;    // 0..3
    const int bh  = blockIdx.z;
    const int q0  = blockIdx.y * 128;
    const int k0g = blockIdx.x * 128;

    const __half* Qb = Qg + (long long)bh * SS * DP + (long long)q0  * DP;
    const __half* Kb = Kg + (long long)bh * SS * DP + (long long)k0g * DP;

    // load both 128x64-half tiles (128 B per row = 8 cp.async each)
#pragma unroll
    for (int i = 0; i < 4; i++) {
        int idx = tid + i * 256;          // 0..1023
        int r   = idx >> 3;               // row
        int c8  = (idx & 7) * 8;          // half offset (16B chunks)
        cp_async16(&Qs[r * STR + c8], Qb + (long long)r * DP + c8);
        cp_async16(&Ks[r * STR + c8], Kb + (long long)r * DP + c8);
    }
    cp_commit();
    cp_wait<0>();
    __syncthreads();

    float acc[4][4][4];
#pragma unroll
    for (int mt = 0; mt < 4; mt++)
#pragma unroll
        for (int nt = 0; nt < 4; nt++)
#pragma unroll
            for (int i = 0; i < 4; i++) acc[mt][nt][i] = 0.0f;

    // fp16 ldmatrix addressing:
    // A (16x16): lanes 0-15 -> rows 0-15 @k+0 ; 16-31 -> rows 0-15 @k+8
    // B (16n x 16k): lanes 0-7 n0-7@k0; 8-15 n0-7@k8; 16-23 n8-15@k0; 24-31 n8-15@k8
    const int a_row = lane & 15;
    const int a_col = (lane >> 4) * 8;
    const int grp = lane >> 3, rrw = lane & 7;
    const int b_row = (grp >> 1) * 8 + rrw;
    const int b_col = (grp & 1) * 8;

#pragma unroll
    for (int ks = 0; ks < 4; ks++) {      // k = ks*16
        unsigned af[4][4];
        unsigned bf[4][2];
#pragma unroll
        for (int mt = 0; mt < 4; mt++)
            ldsm_x4(af[mt], &Qs[(wm * 64 + mt * 16 + a_row) * STR + ks * 16 + a_col]);
#pragma unroll
        for (int np = 0; np < 2; np++) {
            unsigned qv[4];
            ldsm_x4(qv, &Ks[(wn * 32 + np * 16 + b_row) * STR + ks * 16 + b_col]);
            bf[np * 2 + 0][0] = qv[0]; bf[np * 2 + 0][1] = qv[1];
            bf[np * 2 + 1][0] = qv[2]; bf[np * 2 + 1][1] = qv[3];
        }
#pragma unroll
        for (int mt = 0; mt < 4; mt++)
#pragma unroll
            for (int nt = 0; nt < 4; nt++)
                mma_f16(acc[mt][nt], af[mt], bf[nt]);
    }

    // epilogue: scaled raw logits
    float* outp = attn + ((long long)bh * SS + q0) * SS + k0g;
#pragma unroll
    for (int mt = 0; mt < 4; mt++)
#pragma unroll
        for (int nt = 0; nt < 4; nt++)
#pragma unroll
            for (int i = 0; i < 4; i++) {
                int r = wm * 64 + mt * 16 + (lane >> 2) + ((i >= 2) ? 8 : 0);
                int c = wn * 32 + nt * 8 + (lane & 3) * 2 + (i & 1);
                outp[(long long)r * SS + c] = acc[mt][nt][i] * 0.125f;
            }
}

// ---------------------------------------------------------------------------
// In-place row softmax (R10-proven): one 128-thread block per row.
// ---------------------------------------------------------------------------
__global__ __launch_bounds__(128)
void softmax_kernel(float* __restrict__ attn, const float* __restrict__ mask)
{
    const long long row = blockIdx.x;
    const int q = (int)(row % SS);
    float* p = attn + row * SS;
    const float* m = mask + (long long)q * SS;
    const int t = threadIdx.x;

    float4 vals[4];
    float mx = -INFINITY;
#pragma unroll
    for (int i = 0; i < 4; i++) {
        float4 lv = ((const float4*)p)[t + i * 128];
        float4 mv = ((const float4*)m)[t + i * 128];
        lv.x = fmaf(mv.x, -1e9f, lv.x);
        lv.y = fmaf(mv.y, -1e9f, lv.y);
        lv.z = fmaf(mv.z, -1e9f, lv.z);
        lv.w = fmaf(mv.w, -1e9f, lv.w);
        vals[i] = lv;
        mx = fmaxf(mx, fmaxf(fmaxf(lv.x, lv.y), fmaxf(lv.z, lv.w)));
    }

    __shared__ float red[4];
#pragma unroll
    for (int o = 16; o > 0; o >>= 1)
        mx = fmaxf(mx, __shfl_xor_sync(0xffffffffu, mx, o));
    if ((t & 31) == 0) red[t >> 5] = mx;
    __syncthreads();
    mx = fmaxf(fmaxf(red[0], red[1]), fmaxf(red[2], red[3]));
    __syncthreads();

    float ssum = 0.0f;
#pragma unroll
    for (int i = 0; i < 4; i++) {
        vals[i].x = __expf(vals[i].x - mx);
        vals[i].y = __expf(vals[i].y - mx);
        vals[i].z = __expf(vals[i].z - mx);
        vals[i].w = __expf(vals[i].w - mx);
        ssum += vals[i].x + vals[i].y + vals[i].z + vals[i].w;
    }
#pragma unroll
    for (int o = 16; o > 0; o >>= 1)
        ssum += __shfl_xor_sync(0xffffffffu, ssum, o);
    if ((t & 31) == 0) red[t >> 5] = ssum;
    __syncthreads();
    ssum = red[0] + red[1] + red[2] + red[3];
    const float rinv = 1.0f / ssum;

#pragma unroll
    for (int i = 0; i < 4; i++) {
        float4 v = vals[i];
        v.x *= rinv; v.y *= rinv; v.z *= rinv; v.w *= rinv;
        ((float4*)p)[t + i * 128] = v;
    }
}

// ---------------------------------------------------------------------------
extern "C" void kernel_launch(void* const* d_in, const int* in_sizes, int n_in,
                              void* d_out, int out_size)
{
    const float* q    = (const float*)d_in[0];
    const float* k    = (const float*)d_in[1];
    const float* v    = (const float*)d_in[2];
    const float* mask = (const float*)d_in[3];
    const float* Wq   = (const float*)d_in[4];
    const float* bq   = (const float*)d_in[5];
    const float* Wk   = (const float*)d_in[6];
    const float* bk   = (const float*)d_in[7];
    const float* Wv   = (const float*)d_in[8];
    const float* bv   = (const float*)d_in[9];
    const float* Wo   = (const float*)d_in[10];
    const float* bo   = (const float*)d_in[11];

    float* outp  = (float*)d_out;
    float* attnp = nullptr;
    if ((long long)out_size >= OUT_ELEMS + ATTN_ELEMS) {
        attnp = outp + OUT_ELEMS;
    } else {
        void* sym = nullptr;
        cudaGetSymbolAddress(&sym, g_attn);
        attnp = (float*)sym;
    }

    __half* Qh = nullptr; cudaGetSymbolAddress((void**)&Qh, g_Qh16);
    __half* Kh = nullptr; cudaGetSymbolAddress((void**)&Kh, g_Kh16);
    float* Vh  = nullptr; cudaGetSymbolAddress((void**)&Vh,  g_Vh);
    float* ctx = nullptr; cudaGetSymbolAddress((void**)&ctx, g_ctx);

    // --- Q/K projections -> fp16 head-split; V -> fp32 head-split ---
    mma_gemm_kernel<128,128,16,64,32,false,4,256><<<dim3(8,64,1), 256>>>(
        q, Wq, bq, (float*)Qh, MM, DD, DD, 0, 0, 0, 1.0f);
    mma_gemm_kernel<128,128,16,64,32,false,4,256><<<dim3(8,64,1), 256>>>(
        k, Wk, bk, (float*)Kh, MM, DD, DD, 0, 0, 0, 1.0f);
    mma_gemm_kernel<128,128,16,64,32,false,1,256><<<dim3(8,64,1), 256>>>(
        v, Wv, bv, Vh, MM, DD, DD, 0, 0, 0, 1.0f);

    // --- logits = (Q @ K^T) / 8 in fp16 tensor cores ---
    qk16_kernel<<<dim3(16,16,BB*HH), 256>>>(Qh, Kh, attnp);

    // --- softmax in place (with mask) ---
    softmax_kernel<<<BB*HH*SS, 128>>>(attnp, mask);

    // --- ctx = attn @ V, merged layout (tf32 path, R10-proven) ---
    mma_gemm_kernel<128,64,16,32,32,false,2,256><<<dim3(1,16,BB*HH), 256>>>(
        attnp, Vh, nullptr, ctx, SS, DP, SS,
        (long long)SS*SS, (long long)SS*DP, 0, 1.0f);

    // --- output projection ---
    mma_gemm_kernel<128,128,16,64,32,false,0,256><<<dim3(8,64,1), 256>>>(
        ctx, Wo, bo, outp, MM, DD, DD, 0, 0, 0, 1.0f);
}

// round 17
// speedup vs baseline: 1.3999x; 1.3999x over previous
#include <cuda_runtime.h>
#include <cuda_bf16.h>
#include <math.h>

#define BB 4
#define SS 2048
#define DD 1024
#define HH 16
#define DP 64
#define MM (BB*SS)

static const long long OUT_ELEMS  = (long long)BB*SS*DD;
static const long long ATTN_ELEMS = (long long)BB*HH*(long long)SS*SS;

// Scratch (__device__ globals per allocation rules)
__device__ float g_Qh[BB*HH*SS*DP];
__device__ float g_Kh[BB*HH*SS*DP];
__device__ float g_Vh[BB*HH*SS*DP];
__device__ float g_ctx[BB*SS*DD];
__device__ float g_attn[BB*HH*(long long)SS*SS];

// ---------------------------------------------------------------------------
__device__ __forceinline__ unsigned f2tf(float x) {
    unsigned r;
    asm("cvt.rna.tf32.f32 %0, %1;" : "=r"(r) : "f"(x));
    return r;
}
__device__ __forceinline__ unsigned raw2tf(unsigned x) {
    return f2tf(__uint_as_float(x));
}

__device__ __forceinline__ void mma_tf32(float c[4], const unsigned a[4], const unsigned b[2]) {
    asm volatile(
        "mma.sync.aligned.m16n8k8.row.col.f32.tf32.tf32.f32 "
        "{%0,%1,%2,%3}, {%4,%5,%6,%7}, {%8,%9}, {%0,%1,%2,%3};"
        : "+f"(c[0]), "+f"(c[1]), "+f"(c[2]), "+f"(c[3])
        : "r"(a[0]), "r"(a[1]), "r"(a[2]), "r"(a[3]), "r"(b[0]), "r"(b[1]));
}

// ldmatrix x4 (b16 view of b32 quads) — fragment mapping verified in R5.
__device__ __forceinline__ void ldsm_x4(unsigned r[4], const unsigned* p) {
    unsigned addr = (unsigned)__cvta_generic_to_shared(p);
    asm volatile("ldmatrix.sync.aligned.m8n8.x4.shared.b16 {%0,%1,%2,%3}, [%4];"
                 : "=r"(r[0]), "=r"(r[1]), "=r"(r[2]), "=r"(r[3]) : "r"(addr));
}

__device__ __forceinline__ void cp_async16(unsigned* smem, const float* gmem) {
    unsigned s = (unsigned)__cvta_generic_to_shared(smem);
    asm volatile("cp.async.ca.shared.global [%0], [%1], 16;" :: "r"(s), "l"(gmem));
}
__device__ __forceinline__ void cp_commit() {
    asm volatile("cp.async.commit_group;");
}
template<int N>
__device__ __forceinline__ void cp_wait() {
    asm volatile("cp.async.wait_group %0;" :: "n"(N));
}

// ---------------------------------------------------------------------------
// Pipelined TF32 tensor-core GEMM:  C = alpha * A @ op(B) + bias
//  BT=false: B [K,N] row-major, Bs[k][n], scalar B fragments.
//  BT=true : B [N,K] row-major, Bs[n][k], ldmatrix B fragments (NT even).
//  SPLIT: 0 = C[z*sC + r*N+c]; 1 = head-split [b,h,s,d]; 2 = merged ctx.
//  For BT && SPLIT==0 (the QK^T launch) the epilogue is staged through the
//  dead double-buffer smem so gmem stores are 128B-coalesced float4 rows.
// ---------------------------------------------------------------------------
template<int BM, int BN, int BK, int WM, int WN, bool BT, int SPLIT, int THREADS>
__global__ __launch_bounds__(THREADS)
void mma_gemm_kernel(const float* __restrict__ A,
                     const float* __restrict__ Bm,
                     const float* __restrict__ bias,
                     float* __restrict__ C,
                     int M, int N, int K,
                     long long sA, long long sB, long long sC,
                     float alpha)
{
    constexpr int AP  = BK + 4;
    constexpr int BP  = BN + 4;
    constexpr int BP2 = BK + 4;
    constexpr int ASZ = BM * AP;
    constexpr int BSZ = BT ? (BN * BP2) : (BK * BP);
    __shared__ __align__(16) unsigned As[2 * ASZ];
    __shared__ __align__(16) unsigned Bs[2 * BSZ];

    const int tid  = threadIdx.x;
    const int lane = tid & 31;
    const int warp = tid >> 5;
    constexpr int WN_CNT = BN / WN;
    const int wm = warp / WN_CNT;
    const int wn = warp % WN_CNT;
    const int row0 = blockIdx.y * BM;
    const int col0 = blockIdx.x * BN;
    const int z    = blockIdx.z;

    A  += (long long)z * sA;
    Bm += (long long)z * sB;

    constexpr int MT = WM / 16;
    constexpr int NT = WN / 8;
    float cfr[MT][NT][4];
#pragma unroll
    for (int mt = 0; mt < MT; mt++)
#pragma unroll
        for (int nt = 0; nt < NT; nt++)
#pragma unroll
            for (int i = 0; i < 4; i++) cfr[mt][nt][i] = 0.0f;

    const int grp  = lane >> 3, rrw = lane & 7;
    const int a_ro = (grp & 1) * 8 + rrw;
    const int a_ko = (grp >> 1) * 4;
    const int b_no = (grp >> 1) * 8 + rrw;
    const int b_ko = (grp & 1) * 4;

    auto load_tiles = [&](int buf, int k0) {
        unsigned* Ad = As + buf * ASZ;
        unsigned* Bd = Bs + buf * BSZ;
#pragma unroll
        for (int i = 0; i < (BM * (BK / 4)) / THREADS; i++) {
            int idx = tid + i * THREADS;
            int r   = idx / (BK / 4);
            int kq  = (idx % (BK / 4)) * 4;
            cp_async16(&Ad[r * AP + kq], A + (long long)(row0 + r) * K + k0 + kq);
        }
        if (BT) {
#pragma unroll
            for (int i = 0; i < (BN * (BK / 4)) / THREADS; i++) {
                int idx = tid + i * THREADS;
                int n   = idx / (BK / 4);
                int kq  = (idx % (BK / 4)) * 4;
                cp_async16(&Bd[n * BP2 + kq], Bm + (long long)(col0 + n) * K + k0 + kq);
            }
        } else {
#pragma unroll
            for (int i = 0; i < (BK * (BN / 4)) / THREADS; i++) {
                int idx = tid + i * THREADS;
                int kk  = idx / (BN / 4);
                int nq  = (idx % (BN / 4)) * 4;
                cp_async16(&Bd[kk * BP + nq], Bm + (long long)(k0 + kk) * N + col0 + nq);
            }
        }
        cp_commit();
    };

    const int NK = K / BK;
    load_tiles(0, 0);

    for (int it = 0; it < NK; it++) {
        if (it + 1 < NK) {
            load_tiles((it + 1) & 1, (it + 1) * BK);
            cp_wait<1>();
        } else {
            cp_wait<0>();
        }
        __syncthreads();

        const unsigned* Ab = As + (it & 1) * ASZ;
        const unsigned* Bb = Bs + (it & 1) * BSZ;
#pragma unroll
        for (int ks = 0; ks < BK / 8; ks++) {
            unsigned af[MT][4];
            unsigned bf[NT][2];
#pragma unroll
            for (int mt = 0; mt < MT; mt++) {
                ldsm_x4(af[mt], &Ab[(wm * WM + mt * 16 + a_ro) * AP + ks * 8 + a_ko]);
#pragma unroll
                for (int j = 0; j < 4; j++) af[mt][j] = raw2tf(af[mt][j]);
            }
            if (BT) {
#pragma unroll
                for (int np = 0; np < NT / 2; np++) {
                    unsigned qv[4];
                    ldsm_x4(qv, &Bb[(wn * WN + np * 16 + b_no) * BP2 + ks * 8 + b_ko]);
                    bf[np * 2 + 0][0] = raw2tf(qv[0]); bf[np * 2 + 0][1] = raw2tf(qv[1]);
                    bf[np * 2 + 1][0] = raw2tf(qv[2]); bf[np * 2 + 1][1] = raw2tf(qv[3]);
                }
            } else {
                const int kb = ks * 8 + (lane & 3);
#pragma unroll
                for (int nt = 0; nt < NT; nt++) {
                    int cc = wn * WN + nt * 8 + (lane >> 2);
                    bf[nt][0] = raw2tf(Bb[kb * BP + cc]);
                    bf[nt][1] = raw2tf(Bb[(kb + 4) * BP + cc]);
                }
            }
#pragma unroll
            for (int mt = 0; mt < MT; mt++)
#pragma unroll
                for (int nt = 0; nt < NT; nt++)
                    mma_tf32(cfr[mt][nt], af[mt], bf[nt]);
        }
        __syncthreads();
    }

    // ======================= epilogue =======================
    if (BT && SPLIT == 0) {
        // Staged coalesced store (QK^T path, store-bound): 64 rows per pass.
        // Dead pipeline smem (2*ASZ + 2*BSZ words >= 64*132) reused as floats.
        float* Cs = (float*)As;
        constexpr int CSTR = BN + 4;           // 132
        static_assert(2 * ASZ + 2 * BSZ >= 64 * CSTR, "stage smem");
        constexpr int HALF = WM;               // 64 rows per wm group (MT*16)
#pragma unroll
        for (int p = 0; p < BM / HALF; p++) {
            __syncthreads();
            if (wm == p) {
#pragma unroll
                for (int mt = 0; mt < MT; mt++)
#pragma unroll
                    for (int nt = 0; nt < NT; nt++)
#pragma unroll
                        for (int i = 0; i < 4; i++) {
                            int rl = mt * 16 + (lane >> 2) + ((i >= 2) ? 8 : 0);
                            int c  = wn * WN + nt * 8 + (lane & 3) * 2 + (i & 1);
                            Cs[rl * CSTR + c] = cfr[mt][nt][i] * alpha;
                        }
            }
            __syncthreads();
            // 64 rows x BN cols, float4-coalesced
#pragma unroll
            for (int i = 0; i < (HALF * (BN / 4)) / THREADS; i++) {
                int idx = tid + i * THREADS;
                int r2  = idx / (BN / 4);
                int c4  = (idx % (BN / 4)) * 4;
                float4 v = *(float4*)&Cs[r2 * CSTR + c4];
                *(float4*)(C + (long long)z * sC +
                           (long long)(row0 + p * HALF + r2) * N + col0 + c4) = v;
            }
        }
    } else {
#pragma unroll
        for (int mt = 0; mt < MT; mt++) {
#pragma unroll
            for (int nt = 0; nt < NT; nt++) {
#pragma unroll
                for (int i = 0; i < 4; i++) {
                    int r = row0 + wm * WM + mt * 16 + (lane >> 2) + ((i >= 2) ? 8 : 0);
                    int c = col0 + wn * WN + nt * 8 + (lane & 3) * 2 + (i & 1);
                    float v = cfr[mt][nt][i] * alpha + (bias ? bias[c] : 0.0f);
                    if (SPLIT == 0) {
                        C[(long long)z * sC + (long long)r * N + c] = v;
                    } else if (SPLIT == 1) {
                        int b = r / SS, s = r % SS;
                        int h = c / DP, d = c % DP;
                        C[(((long long)b * HH + h) * SS + s) * DP + d] = v;
                    } else {
                        int b = z / HH, h = z % HH;
                        C[((long long)b * SS + r) * DD + h * DP + c] = v;
                    }
                }
            }
        }
    }
}

// ---------------------------------------------------------------------------
// In-place row softmax: one 128-thread block per row, row in registers.
// ---------------------------------------------------------------------------
__global__ __launch_bounds__(128)
void softmax_kernel(float* __restrict__ attn, const float* __restrict__ mask)
{
    const long long row = blockIdx.x;
    const int q = (int)(row % SS);
    float* p = attn + row * SS;
    const float* m = mask + (long long)q * SS;
    const int t = threadIdx.x;

    float4 vals[4];
    float mx = -INFINITY;
#pragma unroll
    for (int i = 0; i < 4; i++) {
        float4 lv = ((const float4*)p)[t + i * 128];
        float4 mv = ((const float4*)m)[t + i * 128];
        lv.x = fmaf(mv.x, -1e9f, lv.x);
        lv.y = fmaf(mv.y, -1e9f, lv.y);
        lv.z = fmaf(mv.z, -1e9f, lv.z);
        lv.w = fmaf(mv.w, -1e9f, lv.w);
        vals[i] = lv;
        mx = fmaxf(mx, fmaxf(fmaxf(lv.x, lv.y), fmaxf(lv.z, lv.w)));
    }

    __shared__ float red[4];
#pragma unroll
    for (int o = 16; o > 0; o >>= 1)
        mx = fmaxf(mx, __shfl_xor_sync(0xffffffffu, mx, o));
    if ((t & 31) == 0) red[t >> 5] = mx;
    __syncthreads();
    mx = fmaxf(fmaxf(red[0], red[1]), fmaxf(red[2], red[3]));
    __syncthreads();

    float ssum = 0.0f;
#pragma unroll
    for (int i = 0; i < 4; i++) {
        vals[i].x = __expf(vals[i].x - mx);
        vals[i].y = __expf(vals[i].y - mx);
        vals[i].z = __expf(vals[i].z - mx);
        vals[i].w = __expf(vals[i].w - mx);
        ssum += vals[i].x + vals[i].y + vals[i].z + vals[i].w;
    }
#pragma unroll
    for (int o = 16; o > 0; o >>= 1)
        ssum += __shfl_xor_sync(0xffffffffu, ssum, o);
    if ((t & 31) == 0) red[t >> 5] = ssum;
    __syncthreads();
    ssum = red[0] + red[1] + red[2] + red[3];
    const float rinv = 1.0f / ssum;

#pragma unroll
    for (int i = 0; i < 4; i++) {
        float4 v = vals[i];
        v.x *= rinv; v.y *= rinv; v.z *= rinv; v.w *= rinv;
        ((float4*)p)[t + i * 128] = v;
    }
}

// ---------------------------------------------------------------------------
extern "C" void kernel_launch(void* const* d_in, const int* in_sizes, int n_in,
                              void* d_out, int out_size)
{
    const float* q    = (const float*)d_in[0];
    const float* k    = (const float*)d_in[1];
    const float* v    = (const float*)d_in[2];
    const float* mask = (const float*)d_in[3];
    const float* Wq   = (const float*)d_in[4];
    const float* bq   = (const float*)d_in[5];
    const float* Wk   = (const float*)d_in[6];
    const float* bk   = (const float*)d_in[7];
    const float* Wv   = (const float*)d_in[8];
    const float* bv   = (const float*)d_in[9];
    const float* Wo   = (const float*)d_in[10];
    const float* bo   = (const float*)d_in[11];

    float* outp  = (float*)d_out;
    float* attnp = nullptr;
    if ((long long)out_size >= OUT_ELEMS + ATTN_ELEMS) {
        attnp = outp + OUT_ELEMS;
    } else {
        void* sym = nullptr;
        cudaGetSymbolAddress(&sym, g_attn);
        attnp = (float*)sym;
    }

    float* Qh = nullptr;  cudaGetSymbolAddress((void**)&Qh,  g_Qh);
    float* Kh = nullptr;  cudaGetSymbolAddress((void**)&Kh,  g_Kh);
    float* Vh = nullptr;  cudaGetSymbolAddress((void**)&Vh,  g_Vh);
    float* ctx = nullptr; cudaGetSymbolAddress((void**)&ctx, g_ctx);

    // --- Q/K/V projections (head-split outputs) ---
    mma_gemm_kernel<128,128,16,64,32,false,1,256><<<dim3(8,64,1), 256>>>(
        q, Wq, bq, Qh, MM, DD, DD, 0, 0, 0, 1.0f);
    mma_gemm_kernel<128,128,16,64,32,false,1,256><<<dim3(8,64,1), 256>>>(
        k, Wk, bk, Kh, MM, DD, DD, 0, 0, 0, 1.0f);
    mma_gemm_kernel<128,128,16,64,32,false,1,256><<<dim3(8,64,1), 256>>>(
        v, Wv, bv, Vh, MM, DD, DD, 0, 0, 0, 1.0f);

    // --- logits = (Q @ K^T) / 8, batched over 64 (b,h); staged epilogue ---
    mma_gemm_kernel<128,128,16,64,32,true,0,256><<<dim3(16,16,BB*HH), 256>>>(
        Qh, Kh, nullptr, attnp, SS, SS, DP,
        (long long)SS*DP, (long long)SS*DP, (long long)SS*SS, 0.125f);

    // --- softmax in place (with mask) ---
    softmax_kernel<<<BB*HH*SS, 128>>>(attnp, mask);

    // --- ctx = attn @ V, merged layout (R10-proven config) ---
    mma_gemm_kernel<128,64,16,32,32,false,2,256><<<dim3(1,16,BB*HH), 256>>>(
        attnp, Vh, nullptr, ctx, SS, DP, SS,
        (long long)SS*SS, (long long)SS*DP, 0, 1.0f);

    // --- output projection ---
    mma_gemm_kernel<128,128,16,64,32,false,0,256><<<dim3(8,64,1), 256>>>(
        ctx, Wo, bo, outp, MM, DD, DD, 0, 0, 0, 1.0f);
}